// round 1
// baseline (speedup 1.0000x reference)
#include <cuda_runtime.h>
#include <cuda_bf16.h>
#include <math_constants.h>

// Problem constants (fixed by the dataset)
#define PP 16
#define CC 4
#define KK 8
#define NN 65536
#define DD 256
#define NROWS 64            // P*C
#define TILE_N 128
#define NB (NN / TILE_N)    // 512 blocks
#define INV_TEMP 20.0f

// Scratch (no allocations allowed)
__device__ float g_xbT[DD * NROWS];          // x-bar transposed: [k][row], k-major
__device__ float g_pm[NROWS * NB];           // per-block running max
__device__ float g_ps[NROWS * NB];           // per-block sum of exp(v - max)
__device__ float g_pmin[NROWS * NB];         // per-block min

// ---------------------------------------------------------------------------
// Kernel A: normalize each of the 512 input rows, average groups of K=8,
// store transposed (k-major) for the GEMM.
// grid = 64 (one block per (p,c) row), block = 256 (= D)
// ---------------------------------------------------------------------------
__global__ void prep_kernel(const float* __restrict__ inputs) {
    const int pc = blockIdx.x;
    const int t  = threadIdx.x;           // dimension index d
    __shared__ float wsum[8];

    float acc = 0.0f;
    for (int k = 0; k < KK; k++) {
        float v = inputs[(size_t)(pc * KK + k) * DD + t];
        float sq = v * v;
        #pragma unroll
        for (int off = 16; off; off >>= 1)
            sq += __shfl_xor_sync(0xFFFFFFFFu, sq, off);
        if ((t & 31) == 0) wsum[t >> 5] = sq;
        __syncthreads();
        float s2 = 0.0f;
        #pragma unroll
        for (int w = 0; w < 8; w++) s2 += wsum[w];
        acc += v * rsqrtf(s2);
        __syncthreads();   // protect wsum before next iteration overwrites
    }
    g_xbT[t * NROWS + pc] = acc * (1.0f / (float)KK);
}

// ---------------------------------------------------------------------------
// Kernel B: for a TILE_N slab of features, compute dot[64][TILE_N]*20 and
// reduce per row to (running max, sum-exp, min). grid = NB, block = 256.
// Microtile per thread: 8 rows x 4 cols. Warp = one row-group (trow).
// smem: xbs[256][64] (k-major, bcast reads) + fts[128][257] (n-major, padded)
// ---------------------------------------------------------------------------
#define FT_STRIDE 257
__global__ void gemm_reduce_kernel(const float* __restrict__ features) {
    extern __shared__ float sm[];
    float* xbs = sm;                       // 256*64 = 16384 floats
    float* fts = sm + DD * NROWS;          // 128*257 = 32896 floats

    const int t  = threadIdx.x;            // 256 threads
    const int b  = blockIdx.x;
    const int n0 = b * TILE_N;

    // ---- load x-bar (already k-major) ----
    {
        const float4* src = (const float4*)g_xbT;
        float4* dst = (float4*)xbs;
        for (int i = t; i < (DD * NROWS) / 4; i += 256) dst[i] = src[i];
    }
    // ---- load features slab, n-major with pad-257 (scalar STS, 4-way ok) ----
    {
        const float4* f4 = (const float4*)(features + (size_t)n0 * DD);
        for (int i = t; i < TILE_N * (DD / 4); i += 256) {
            int n  = i >> 6;           // 64 float4 per row
            int kq = i & 63;
            float4 v = f4[(size_t)n * 64 + kq];
            float* dst = fts + n * FT_STRIDE + kq * 4;
            dst[0] = v.x; dst[1] = v.y; dst[2] = v.z; dst[3] = v.w;
        }
    }
    __syncthreads();

    const int tcol = t & 31;               // lane -> strided n columns
    const int trow = t >> 5;               // warp -> 8-row group

    float acc[8][4];
    #pragma unroll
    for (int i = 0; i < 8; i++)
        #pragma unroll
        for (int j = 0; j < 4; j++) acc[i][j] = 0.0f;

    const float4* ap = (const float4*)(xbs + trow * 8); // 32B aligned
    const float* bp0 = fts + (tcol +  0) * FT_STRIDE;
    const float* bp1 = fts + (tcol + 32) * FT_STRIDE;
    const float* bp2 = fts + (tcol + 64) * FT_STRIDE;
    const float* bp3 = fts + (tcol + 96) * FT_STRIDE;

    #pragma unroll 8
    for (int k = 0; k < DD; k++) {
        float4 a0 = ap[k * 16];
        float4 a1 = ap[k * 16 + 1];
        float bq0 = bp0[k], bq1 = bp1[k], bq2 = bp2[k], bq3 = bp3[k];
        float a[8] = {a0.x, a0.y, a0.z, a0.w, a1.x, a1.y, a1.z, a1.w};
        #pragma unroll
        for (int i = 0; i < 8; i++) {
            acc[i][0] = fmaf(a[i], bq0, acc[i][0]);
            acc[i][1] = fmaf(a[i], bq1, acc[i][1]);
            acc[i][2] = fmaf(a[i], bq2, acc[i][2]);
            acc[i][3] = fmaf(a[i], bq3, acc[i][3]);
        }
    }

    // ---- fused reduction: per row -> (max, sum exp, min) over 128 cols ----
    #pragma unroll
    for (int i = 0; i < 8; i++) {
        const int row = trow * 8 + i;
        float m = -CUDART_INF_F, s = 0.0f, mn = CUDART_INF_F;
        #pragma unroll
        for (int j = 0; j < 4; j++) {
            float v = acc[i][j] * INV_TEMP;
            float nm = fmaxf(m, v);
            s = s * __expf(m - nm) + __expf(v - nm);
            m = nm;
            mn = fminf(mn, v);
        }
        #pragma unroll
        for (int off = 16; off; off >>= 1) {
            float mo  = __shfl_xor_sync(0xFFFFFFFFu, m,  off);
            float so  = __shfl_xor_sync(0xFFFFFFFFu, s,  off);
            float mno = __shfl_xor_sync(0xFFFFFFFFu, mn, off);
            float nm = fmaxf(m, mo);
            s = s * __expf(m - nm) + so * __expf(mo - nm);
            m = nm;
            mn = fminf(mn, mno);
        }
        if (tcol == 0) {
            g_pm[row * NB + b]   = m;
            g_ps[row * NB + b]   = s;
            g_pmin[row * NB + b] = mn;
        }
    }
}

// ---------------------------------------------------------------------------
// Kernel C: combine partials, compute own/pos, assemble the scalar loss.
// 1 block, 256 threads (8 warps).
// ---------------------------------------------------------------------------
__global__ void finalize_kernel(const float* __restrict__ features,
                                float* __restrict__ out) {
    __shared__ float rM[NROWS], rS[NROWS], rMin[NROWS], sOwn[NROWS];
    const int t = threadIdx.x;
    const int w = t >> 5, l = t & 31;

    // combine the NB block-partials per row
    for (int j = 0; j < 8; j++) {
        const int row = w * 8 + j;
        float m = -CUDART_INF_F, s = 0.0f, mn = CUDART_INF_F;
        for (int q = l; q < NB; q += 32) {
            float pm  = g_pm[row * NB + q];
            float ps  = g_ps[row * NB + q];
            float pmn = g_pmin[row * NB + q];
            float nm = fmaxf(m, pm);
            s = s * expf(m - nm) + ps * expf(pm - nm);
            m = nm;
            mn = fminf(mn, pmn);
        }
        #pragma unroll
        for (int off = 16; off; off >>= 1) {
            float mo  = __shfl_xor_sync(0xFFFFFFFFu, m,  off);
            float so  = __shfl_xor_sync(0xFFFFFFFFu, s,  off);
            float mno = __shfl_xor_sync(0xFFFFFFFFu, mn, off);
            float nm = fmaxf(m, mo);
            s = s * expf(m - nm) + so * expf(mo - nm);
            m = nm;
            mn = fminf(mn, mno);
        }
        if (l == 0) { rM[row] = m; rS[row] = s; rMin[row] = mn; }
    }
    __syncthreads();

    // own[p][c] = 20 * (xbar[pc] . f[p])  -- 64 small dots
    for (int j = 0; j < 8; j++) {
        const int pc = w * 8 + j;
        const int p  = pc >> 2;
        float d = 0.0f;
        for (int q = l; q < DD; q += 32)
            d = fmaf(g_xbT[q * NROWS + pc], features[(size_t)p * DD + q], d);
        #pragma unroll
        for (int off = 16; off; off >>= 1)
            d += __shfl_xor_sync(0xFFFFFFFFu, d, off);
        if (l == 0) sOwn[pc] = d * INV_TEMP;
    }
    __syncthreads();

    float loss = 0.0f;
    if (t < PP) {
        const int p = t;
        float m = -CUDART_INF_F;
        #pragma unroll
        for (int c = 0; c < CC; c++) m = fmaxf(m, rM[p * CC + c]);
        float S = 0.0f;
        #pragma unroll
        for (int c = 0; c < CC; c++)
            S += rS[p * CC + c] * expf(rM[p * CC + c] - m);
        #pragma unroll
        for (int c = 0; c < CC; c++)
            S -= expf(rMin[p * CC + c] - m);
        float pos = CUDART_INF_F;
        #pragma unroll
        for (int c = 0; c < CC; c++) pos = fminf(pos, sOwn[p * CC + c]);
        S += expf(pos - m);
        loss = (m + logf(S)) - pos;
    }
    if (w == 0) {
        #pragma unroll
        for (int off = 16; off; off >>= 1)
            loss += __shfl_xor_sync(0xFFFFFFFFu, loss, off);
        if (l == 0) out[0] = loss * (1.0f / (float)PP);
    }
}

// ---------------------------------------------------------------------------
extern "C" void kernel_launch(void* const* d_in, const int* in_sizes, int n_in,
                              void* d_out, int out_size) {
    const float* inputs   = (const float*)d_in[0];   // [512, 256] f32
    const float* features = (const float*)d_in[4];   // [65536, 256] f32 (normalized)
    float* out = (float*)d_out;

    const size_t smem = (size_t)(DD * NROWS + TILE_N * FT_STRIDE) * sizeof(float);
    cudaFuncSetAttribute(gemm_reduce_kernel,
                         cudaFuncAttributeMaxDynamicSharedMemorySize, (int)smem);

    prep_kernel<<<NROWS, DD>>>(inputs);
    gemm_reduce_kernel<<<NB, 256, smem>>>(features);
    finalize_kernel<<<1, 256>>>(features, out);
}

// round 3
// speedup vs baseline: 1.1890x; 1.1890x over previous
#include <cuda_runtime.h>
#include <cuda_bf16.h>
#include <math_constants.h>

// Problem constants (fixed by the dataset)
#define PP 16
#define CC 4
#define KK 8
#define NN 65536
#define DD 256
#define NROWS 64            // P*C
#define TILE_N 128
#define NB (NN / TILE_N)    // 512 blocks
#define INV_TEMP 20.0f
#define FT_PAD 260          // k-stride of the feature tile (mult of 4, mod 32 == 4)

// Scratch (no allocations allowed)
__device__ float g_xb[NROWS * DD];           // x-bar, row-major [row][k]
__device__ float g_pm[NROWS * NB];           // per-block running max
__device__ float g_ps[NROWS * NB];           // per-block sum of exp(v - max)
__device__ float g_pmin[NROWS * NB];         // per-block min

// packed f32x2 FMA: d += a * b  (element-wise on the two packed floats)
__device__ __forceinline__ void ffma2(unsigned long long& d,
                                      const unsigned long long a,
                                      const unsigned long long b) {
    asm("fma.rn.f32x2 %0, %1, %2, %0;" : "+l"(d) : "l"(a), "l"(b));
}

// ---------------------------------------------------------------------------
// Kernel A: normalize each of the 512 input rows, average groups of K=8,
// store row-major. grid = 64 (one block per (p,c)), block = 256 (= D).
// Single-barrier version: all 8 rows loaded up front.
// ---------------------------------------------------------------------------
__global__ void prep_kernel(const float* __restrict__ inputs) {
    const int pc = blockIdx.x;
    const int t  = threadIdx.x;           // dimension index d
    __shared__ float wsum[8][8];          // [warp][k]

    float v[KK];
    #pragma unroll
    for (int k = 0; k < KK; k++)
        v[k] = inputs[(size_t)(pc * KK + k) * DD + t];

    float sq[KK];
    #pragma unroll
    for (int k = 0; k < KK; k++) sq[k] = v[k] * v[k];
    #pragma unroll
    for (int off = 16; off; off >>= 1)
        #pragma unroll
        for (int k = 0; k < KK; k++)
            sq[k] += __shfl_xor_sync(0xFFFFFFFFu, sq[k], off);
    if ((t & 31) == 0)
        #pragma unroll
        for (int k = 0; k < KK; k++) wsum[t >> 5][k] = sq[k];
    __syncthreads();

    float acc = 0.0f;
    #pragma unroll
    for (int k = 0; k < KK; k++) {
        float s2 = 0.0f;
        #pragma unroll
        for (int w = 0; w < 8; w++) s2 += wsum[w][k];
        acc += v[k] * rsqrtf(s2);
    }
    g_xb[pc * DD + t] = acc * (1.0f / (float)KK);
}

// ---------------------------------------------------------------------------
// Kernel B: TILE_N slab GEMM (FFMA2-packed over k) + fused online-softmax/min.
// grid = NB, block = 256. Thread microtile: 8 rows x 4 cols (cols strided 32).
// smem: xbs[64][256] row-major  +  fts[128][FT_PAD] n-major/k-contig.
// ---------------------------------------------------------------------------
__global__ void gemm_reduce_kernel(const float* __restrict__ features) {
    extern __shared__ float sm[];
    float* xbs = sm;                       // 64*256 = 16384 floats
    float* fts = sm + NROWS * DD;          // 128*260 = 33280 floats

    const int t  = threadIdx.x;            // 256 threads
    const int b  = blockIdx.x;
    const int n0 = b * TILE_N;

    // ---- load x-bar (row-major, linear float4 copy) ----
    {
        const float4* src = (const float4*)g_xb;
        float4* dst = (float4*)xbs;
        #pragma unroll 4
        for (int i = t; i < (NROWS * DD) / 4; i += 256) dst[i] = src[i];
    }
    // ---- load features slab: [n][k] with pad 260 (STS.128, conflict-free) ----
    {
        const float4* f4 = (const float4*)(features + (size_t)n0 * DD);
        #pragma unroll 4
        for (int i = t; i < TILE_N * (DD / 4); i += 256) {
            int n  = i >> 6;           // 64 float4 per feature row
            int kq = i & 63;
            float4 v = f4[(size_t)n * 64 + kq];
            *(float4*)(fts + n * FT_PAD + kq * 4) = v;
        }
    }
    __syncthreads();

    const int tcol = t & 31;               // lane -> strided n columns
    const int trow = t >> 5;               // warp -> 8-row group

    unsigned long long acc[8][4];
    #pragma unroll
    for (int i = 0; i < 8; i++)
        #pragma unroll
        for (int j = 0; j < 4; j++) acc[i][j] = 0ULL;

    const float* arow = xbs + trow * 8 * DD;
    const float* bp0 = fts + (tcol +  0) * FT_PAD;
    const float* bp1 = fts + (tcol + 32) * FT_PAD;
    const float* bp2 = fts + (tcol + 64) * FT_PAD;
    const float* bp3 = fts + (tcol + 96) * FT_PAD;

    #pragma unroll 2
    for (int k = 0; k < DD; k += 4) {
        ulonglong2 b0 = *(const ulonglong2*)(bp0 + k);
        ulonglong2 b1 = *(const ulonglong2*)(bp1 + k);
        ulonglong2 b2 = *(const ulonglong2*)(bp2 + k);
        ulonglong2 b3 = *(const ulonglong2*)(bp3 + k);
        #pragma unroll
        for (int i = 0; i < 8; i++) {
            ulonglong2 a = *(const ulonglong2*)(arow + i * DD + k);
            ffma2(acc[i][0], a.x, b0.x);
            ffma2(acc[i][1], a.x, b1.x);
            ffma2(acc[i][2], a.x, b2.x);
            ffma2(acc[i][3], a.x, b3.x);
            ffma2(acc[i][0], a.y, b0.y);
            ffma2(acc[i][1], a.y, b1.y);
            ffma2(acc[i][2], a.y, b2.y);
            ffma2(acc[i][3], a.y, b3.y);
        }
    }

    // ---- fused reduction: per row -> (max, sum exp, min) over 128 cols ----
    #pragma unroll
    for (int i = 0; i < 8; i++) {
        const int row = trow * 8 + i;
        float m = -CUDART_INF_F, s = 0.0f, mn = CUDART_INF_F;
        #pragma unroll
        for (int j = 0; j < 4; j++) {
            float lo = __uint_as_float((unsigned)(acc[i][j] & 0xFFFFFFFFull));
            float hi = __uint_as_float((unsigned)(acc[i][j] >> 32));
            float v = (lo + hi) * INV_TEMP;
            float nm = fmaxf(m, v);
            s = s * __expf(m - nm) + __expf(v - nm);
            m = nm;
            mn = fminf(mn, v);
        }
        #pragma unroll
        for (int off = 16; off; off >>= 1) {
            float mo  = __shfl_xor_sync(0xFFFFFFFFu, m,  off);
            float so  = __shfl_xor_sync(0xFFFFFFFFu, s,  off);
            float mno = __shfl_xor_sync(0xFFFFFFFFu, mn, off);
            float nm = fmaxf(m, mo);
            s = s * __expf(m - nm) + so * __expf(mo - nm);
            m = nm;
            mn = fminf(mn, mno);
        }
        if (tcol == 0) {
            g_pm[row * NB + b]   = m;
            g_ps[row * NB + b]   = s;
            g_pmin[row * NB + b] = mn;
        }
    }
}

// ---------------------------------------------------------------------------
// Kernel C: combine partials, compute own/pos, assemble the scalar loss.
// 1 block, 256 threads (8 warps).
// ---------------------------------------------------------------------------
__global__ void finalize_kernel(const float* __restrict__ features,
                                float* __restrict__ out) {
    __shared__ float rM[NROWS], rS[NROWS], rMin[NROWS], sOwn[NROWS];
    const int t = threadIdx.x;
    const int w = t >> 5, l = t & 31;

    // combine the NB block-partials per row
    for (int j = 0; j < 8; j++) {
        const int row = w * 8 + j;
        float m = -CUDART_INF_F, s = 0.0f, mn = CUDART_INF_F;
        for (int q = l; q < NB; q += 32) {
            float pm  = g_pm[row * NB + q];
            float ps  = g_ps[row * NB + q];
            float pmn = g_pmin[row * NB + q];
            float nm = fmaxf(m, pm);
            s = s * expf(m - nm) + ps * expf(pm - nm);
            m = nm;
            mn = fminf(mn, pmn);
        }
        #pragma unroll
        for (int off = 16; off; off >>= 1) {
            float mo  = __shfl_xor_sync(0xFFFFFFFFu, m,  off);
            float so  = __shfl_xor_sync(0xFFFFFFFFu, s,  off);
            float mno = __shfl_xor_sync(0xFFFFFFFFu, mn, off);
            float nm = fmaxf(m, mo);
            s = s * expf(m - nm) + so * expf(mo - nm);
            m = nm;
            mn = fminf(mn, mno);
        }
        if (l == 0) { rM[row] = m; rS[row] = s; rMin[row] = mn; }
    }
    __syncthreads();

    // own[p][c] = 20 * (xbar[pc] . f[p])  -- 64 small dots
    for (int j = 0; j < 8; j++) {
        const int pc = w * 8 + j;
        const int p  = pc >> 2;
        float d = 0.0f;
        for (int q = l; q < DD; q += 32)
            d = fmaf(g_xb[pc * DD + q], features[(size_t)p * DD + q], d);
        #pragma unroll
        for (int off = 16; off; off >>= 1)
            d += __shfl_xor_sync(0xFFFFFFFFu, d, off);
        if (l == 0) sOwn[pc] = d * INV_TEMP;
    }
    __syncthreads();

    float loss = 0.0f;
    if (t < PP) {
        const int p = t;
        float m = -CUDART_INF_F;
        #pragma unroll
        for (int c = 0; c < CC; c++) m = fmaxf(m, rM[p * CC + c]);
        float S = 0.0f;
        #pragma unroll
        for (int c = 0; c < CC; c++)
            S += rS[p * CC + c] * expf(rM[p * CC + c] - m);
        #pragma unroll
        for (int c = 0; c < CC; c++)
            S -= expf(rMin[p * CC + c] - m);
        float pos = CUDART_INF_F;
        #pragma unroll
        for (int c = 0; c < CC; c++) pos = fminf(pos, sOwn[p * CC + c]);
        S += expf(pos - m);
        loss = (m + logf(S)) - pos;
    }
    if (w == 0) {
        #pragma unroll
        for (int off = 16; off; off >>= 1)
            loss += __shfl_xor_sync(0xFFFFFFFFu, loss, off);
        if (l == 0) out[0] = loss * (1.0f / (float)PP);
    }
}

// ---------------------------------------------------------------------------
extern "C" void kernel_launch(void* const* d_in, const int* in_sizes, int n_in,
                              void* d_out, int out_size) {
    const float* inputs   = (const float*)d_in[0];   // [512, 256] f32
    const float* features = (const float*)d_in[4];   // [65536, 256] f32 (normalized)
    float* out = (float*)d_out;

    const size_t smem = (size_t)(NROWS * DD + TILE_N * FT_PAD) * sizeof(float);
    cudaFuncSetAttribute(gemm_reduce_kernel,
                         cudaFuncAttributeMaxDynamicSharedMemorySize, (int)smem);

    prep_kernel<<<NROWS, DD>>>(inputs);
    gemm_reduce_kernel<<<NB, 256, smem>>>(features);
    finalize_kernel<<<1, 256>>>(features, out);
}

// round 5
// speedup vs baseline: 1.5643x; 1.3157x over previous
#include <cuda_runtime.h>
#include <cuda_bf16.h>
#include <math_constants.h>
#include <cstdint>

// Problem constants (fixed by the dataset)
#define PP 16
#define CC 4
#define KK 8
#define NN 65536
#define DD 256
#define NROWS 64            // P*C
#define TILE_N 128
#define NB (NN / TILE_N)    // 512 blocks
#define INV_TEMP 20.0f
#define FSTR 264            // bf16 elements per smem tile row (pad 8 -> conflict-free)

// smem layout (bytes); tiles are [rows][FSTR] bf16, k-contiguous
#define SA_H 0                       // Fh: 128 x FSTR  = 67584 B
#define SA_L (SA_H + 128 * FSTR * 2) // Fl: 67584 B
#define SB_H (SA_L + 128 * FSTR * 2) // Xh: 64 x FSTR   = 33792 B
#define SB_L (SB_H + 64 * FSTR * 2)  // Xl: 33792 B
#define SMEM_BYTES (SB_L + 64 * FSTR * 2)   // 202752

// epilogue overlays (after __syncthreads)
#define SRED_STRIDE 66               // floats; sRed[n][pc] 128 x 66

// Scratch
__device__ float          g_xb[NROWS * DD];     // x-bar f32 (finalize)
__device__ __nv_bfloat16  g_xh[NROWS * DD];     // x-bar hi
__device__ __nv_bfloat16  g_xl[NROWS * DD];     // x-bar lo
__device__ float g_pm[NROWS * NB];
__device__ float g_ps[NROWS * NB];
__device__ float g_pmin[NROWS * NB];

// ---------------------------------------------------------------------------
// helpers
// ---------------------------------------------------------------------------
__device__ __forceinline__ uint32_t smem_u32(const void* p) {
    uint32_t a;
    asm("{ .reg .u64 t; cvta.to.shared.u64 t, %1; cvt.u32.u64 %0, t; }"
        : "=r"(a) : "l"(p));
    return a;
}

__device__ __forceinline__ void ldsm4(uint32_t* d, uint32_t a) {
    asm volatile("ldmatrix.sync.aligned.m8n8.x4.shared.b16 {%0,%1,%2,%3}, [%4];"
                 : "=r"(d[0]), "=r"(d[1]), "=r"(d[2]), "=r"(d[3]) : "r"(a));
}

__device__ __forceinline__ void mma16816(float* c, const uint32_t* a,
                                         const uint32_t b0, const uint32_t b1) {
    asm volatile(
        "mma.sync.aligned.m16n8k16.row.col.f32.bf16.bf16.f32 "
        "{%0,%1,%2,%3}, {%4,%5,%6,%7}, {%8,%9}, {%0,%1,%2,%3};"
        : "+f"(c[0]), "+f"(c[1]), "+f"(c[2]), "+f"(c[3])
        : "r"(a[0]), "r"(a[1]), "r"(a[2]), "r"(a[3]), "r"(b0), "r"(b1));
}

__device__ __forceinline__ unsigned pk2(__nv_bfloat16 a, __nv_bfloat16 b) {
    return (unsigned)__bfloat16_as_ushort(a) | ((unsigned)__bfloat16_as_ushort(b) << 16);
}

// ---------------------------------------------------------------------------
// Kernel A: normalize, K-average, split to bf16 hi/lo. grid=64, block=256.
// ---------------------------------------------------------------------------
__global__ void prep_kernel(const float* __restrict__ inputs) {
    const int pc = blockIdx.x;
    const int t  = threadIdx.x;
    __shared__ float wsum[8][8];

    float v[KK];
    #pragma unroll
    for (int k = 0; k < KK; k++)
        v[k] = inputs[(size_t)(pc * KK + k) * DD + t];

    float sq[KK];
    #pragma unroll
    for (int k = 0; k < KK; k++) sq[k] = v[k] * v[k];
    #pragma unroll
    for (int off = 16; off; off >>= 1)
        #pragma unroll
        for (int k = 0; k < KK; k++)
            sq[k] += __shfl_xor_sync(0xFFFFFFFFu, sq[k], off);
    if ((t & 31) == 0)
        #pragma unroll
        for (int k = 0; k < KK; k++) wsum[t >> 5][k] = sq[k];
    __syncthreads();

    float acc = 0.0f;
    #pragma unroll
    for (int k = 0; k < KK; k++) {
        float s2 = 0.0f;
        #pragma unroll
        for (int w = 0; w < 8; w++) s2 += wsum[w][k];
        acc += v[k] * rsqrtf(s2);
    }
    float xb = acc * (1.0f / (float)KK);
    g_xb[pc * DD + t] = xb;
    __nv_bfloat16 h = __float2bfloat16(xb);
    g_xh[pc * DD + t] = h;
    g_xl[pc * DD + t] = __float2bfloat16(xb - __bfloat162float(h));
}

// ---------------------------------------------------------------------------
// Kernel B: bf16x3 warp-MMA GEMM + fused online-softmax/min partials.
// grid = NB (512), block = 256 (8 warps).
// D[n=128][pc=64] = F[128,256] . Xbar^T via 3-term split chain.
// Warp tile 32(n) x 32(pc): warp w -> n in [(w&3)*32, +32), pc in [(w>>2)*32, +32)
// ---------------------------------------------------------------------------
__global__ void __launch_bounds__(256, 1)
gemm_reduce_kernel(const float* __restrict__ features) {
    extern __shared__ char smem[];
    const uint32_t sb = smem_u32(smem);
    const int t = threadIdx.x;
    const int b = blockIdx.x;
    const int n0 = b * TILE_N;

    // ---- load x-bar hi/lo (bf16) into smem tiles ----
    {
        const uint2* xh4 = (const uint2*)g_xh;   // 4 bf16 per uint2
        const uint2* xl4 = (const uint2*)g_xl;
        #pragma unroll 4
        for (int i = t; i < NROWS * (DD / 4); i += 256) {
            int row  = i >> 6;          // 64 quads per row
            int colq = i & 63;
            uint32_t off = (uint32_t)(row * FSTR + colq * 4) * 2;
            *(uint2*)(smem + SB_H + off) = xh4[i];
            *(uint2*)(smem + SB_L + off) = xl4[i];
        }
    }
    // ---- load + split features tile: f32 -> bf16 hi/lo ----
    {
        const float4* f4 = (const float4*)(features + (size_t)n0 * DD);
        #pragma unroll 4
        for (int i = t; i < TILE_N * (DD / 4); i += 256) {
            float4 v = f4[i];
            int row  = i >> 6;
            int colq = i & 63;
            __nv_bfloat16 h0 = __float2bfloat16(v.x);
            __nv_bfloat16 h1 = __float2bfloat16(v.y);
            __nv_bfloat16 h2 = __float2bfloat16(v.z);
            __nv_bfloat16 h3 = __float2bfloat16(v.w);
            __nv_bfloat16 l0 = __float2bfloat16(v.x - __bfloat162float(h0));
            __nv_bfloat16 l1 = __float2bfloat16(v.y - __bfloat162float(h1));
            __nv_bfloat16 l2 = __float2bfloat16(v.z - __bfloat162float(h2));
            __nv_bfloat16 l3 = __float2bfloat16(v.w - __bfloat162float(h3));
            uint32_t off = (uint32_t)(row * FSTR + colq * 4) * 2;
            *(uint2*)(smem + SA_H + off) = make_uint2(pk2(h0, h1), pk2(h2, h3));
            *(uint2*)(smem + SA_L + off) = make_uint2(pk2(l0, l1), pk2(l2, l3));
        }
    }
    __syncthreads();

    const int lane  = t & 31;
    const int w     = t >> 5;
    const int nbase = (w & 3) * 32;      // feature-row base of warp tile
    const int pcbas = (w >> 2) * 32;     // pc-col base of warp tile

    // ldmatrix per-thread addresses (element offsets within a tile)
    // A (m16 x k16): lane l -> row = (l%8) + ((l/8)%2)*8, col = (l/16)*8
    const int aRow = nbase + (lane & 7) + ((lane >> 3) & 1) * 8;
    const int aCol = (lane >> 4) * 8;
    // B (two pc8-tiles per x4): lane l -> row = (l/16)*8 + l%8, col = ((l/8)%2)*8
    const int bRow = pcbas + (lane & 7) + (lane >> 4) * 8;
    const int bCol = ((lane >> 3) & 1) * 8;

    const uint32_t aOff = (uint32_t)(aRow * FSTR + aCol) * 2;
    const uint32_t bOff = (uint32_t)(bRow * FSTR + bCol) * 2;
    const uint32_t aH = sb + SA_H + aOff, aL = sb + SA_L + aOff;
    const uint32_t bH = sb + SB_H + bOff, bL = sb + SB_L + bOff;

    float acc[2][4][4];
    #pragma unroll
    for (int i = 0; i < 2; i++)
        #pragma unroll
        for (int j = 0; j < 4; j++)
            #pragma unroll
            for (int q = 0; q < 4; q++) acc[i][j][q] = 0.0f;

    #pragma unroll 1
    for (int term = 0; term < 3; term++) {
        const uint32_t aBase = (term == 1) ? aL : aH;
        const uint32_t bBase = (term == 2) ? bL : bH;
        #pragma unroll 4
        for (int k0 = 0; k0 < DD; k0 += 16) {
            uint32_t af[2][4], bf[2][4];
            ldsm4(af[0], aBase + k0 * 2);
            ldsm4(af[1], aBase + k0 * 2 + 16 * FSTR * 2);
            ldsm4(bf[0], bBase + k0 * 2);
            ldsm4(bf[1], bBase + k0 * 2 + 16 * FSTR * 2);
            #pragma unroll
            for (int mt = 0; mt < 2; mt++)
                #pragma unroll
                for (int ntp = 0; ntp < 2; ntp++) {
                    mma16816(acc[mt][ntp * 2 + 0], af[mt], bf[ntp][0], bf[ntp][1]);
                    mma16816(acc[mt][ntp * 2 + 1], af[mt], bf[ntp][2], bf[ntp][3]);
                }
        }
    }
    __syncthreads();   // done reading tiles; safe to overlay epilogue buffers

    // ---- scatter accums to sRed[n][pc] (stride 66) ----
    float* sRed = (float*)smem;                      // 128*66 floats = 33792 B
    {
        const int r0 = lane >> 2;            // 0..7
        const int c0 = (lane & 3) * 2;       // 0,2,4,6
        #pragma unroll
        for (int mt = 0; mt < 2; mt++)
            #pragma unroll
            for (int nt = 0; nt < 4; nt++) {
                const int n  = nbase + mt * 16 + r0;
                const int pc = pcbas + nt * 8 + c0;
                *(float2*)(sRed + n * SRED_STRIDE + pc) =
                    make_float2(acc[mt][nt][0], acc[mt][nt][1]);
                *(float2*)(sRed + (n + 8) * SRED_STRIDE + pc) =
                    make_float2(acc[mt][nt][2], acc[mt][nt][3]);
            }
    }
    __syncthreads();

    // ---- fused reduction: per pc column over 128 n-rows ----
    float* cm = (float*)(smem + SA_L);
    float* cs = cm + 256;
    float* cn = cm + 512;
    {
        const int col = t & 63;              // pc
        const int seg = t >> 6;              // 32-row segment
        const float* src = sRed + (seg * 32) * SRED_STRIDE + col;
        float m = -CUDART_INF_F, s = 0.0f, mn = CUDART_INF_F;
        #pragma unroll 8
        for (int j = 0; j < 32; j++) {
            float v = src[j * SRED_STRIDE] * INV_TEMP;
            float nm = fmaxf(m, v);
            s = s * __expf(m - nm) + __expf(v - nm);
            m = nm;
            mn = fminf(mn, v);
        }
        cm[seg * 64 + col] = m;
        cs[seg * 64 + col] = s;
        cn[seg * 64 + col] = mn;
    }
    __syncthreads();

    if (t < 64) {
        float m = -CUDART_INF_F, s = 0.0f, mn = CUDART_INF_F;
        #pragma unroll
        for (int seg = 0; seg < 4; seg++) {
            float pm = cm[seg * 64 + t], ps = cs[seg * 64 + t], pn = cn[seg * 64 + t];
            float nm = fmaxf(m, pm);
            s = s * __expf(m - nm) + ps * __expf(pm - nm);
            m = nm;
            mn = fminf(mn, pn);
        }
        g_pm[t * NB + b]   = m;
        g_ps[t * NB + b]   = s;
        g_pmin[t * NB + b] = mn;
    }
}

// ---------------------------------------------------------------------------
// Kernel C: combine partials, compute own/pos, assemble the scalar loss.
// ---------------------------------------------------------------------------
__global__ void finalize_kernel(const float* __restrict__ features,
                                float* __restrict__ out) {
    __shared__ float rM[NROWS], rS[NROWS], rMin[NROWS], sOwn[NROWS];
    const int t = threadIdx.x;
    const int w = t >> 5, l = t & 31;

    for (int j = 0; j < 8; j++) {
        const int row = w * 8 + j;
        float m = -CUDART_INF_F, s = 0.0f, mn = CUDART_INF_F;
        for (int q = l; q < NB; q += 32) {
            float pm  = g_pm[row * NB + q];
            float ps  = g_ps[row * NB + q];
            float pmn = g_pmin[row * NB + q];
            float nm = fmaxf(m, pm);
            s = s * expf(m - nm) + ps * expf(pm - nm);
            m = nm;
            mn = fminf(mn, pmn);
        }
        #pragma unroll
        for (int off = 16; off; off >>= 1) {
            float mo  = __shfl_xor_sync(0xFFFFFFFFu, m,  off);
            float so  = __shfl_xor_sync(0xFFFFFFFFu, s,  off);
            float mno = __shfl_xor_sync(0xFFFFFFFFu, mn, off);
            float nm = fmaxf(m, mo);
            s = s * expf(m - nm) + so * expf(mo - nm);
            m = nm;
            mn = fminf(mn, mno);
        }
        if (l == 0) { rM[row] = m; rS[row] = s; rMin[row] = mn; }
    }
    __syncthreads();

    for (int j = 0; j < 8; j++) {
        const int pc = w * 8 + j;
        const int p  = pc >> 2;
        float d = 0.0f;
        for (int q = l; q < DD; q += 32)
            d = fmaf(g_xb[pc * DD + q], features[(size_t)p * DD + q], d);
        #pragma unroll
        for (int off = 16; off; off >>= 1)
            d += __shfl_xor_sync(0xFFFFFFFFu, d, off);
        if (l == 0) sOwn[pc] = d * INV_TEMP;
    }
    __syncthreads();

    float loss = 0.0f;
    if (t < PP) {
        const int p = t;
        float m = -CUDART_INF_F;
        #pragma unroll
        for (int c = 0; c < CC; c++) m = fmaxf(m, rM[p * CC + c]);
        float S = 0.0f;
        #pragma unroll
        for (int c = 0; c < CC; c++)
            S += rS[p * CC + c] * expf(rM[p * CC + c] - m);
        #pragma unroll
        for (int c = 0; c < CC; c++)
            S -= expf(rMin[p * CC + c] - m);
        float pos = CUDART_INF_F;
        #pragma unroll
        for (int c = 0; c < CC; c++) pos = fminf(pos, sOwn[p * CC + c]);
        S += expf(pos - m);
        loss = (m + logf(S)) - pos;
    }
    if (w == 0) {
        #pragma unroll
        for (int off = 16; off; off >>= 1)
            loss += __shfl_xor_sync(0xFFFFFFFFu, loss, off);
        if (l == 0) out[0] = loss * (1.0f / (float)PP);
    }
}

// ---------------------------------------------------------------------------
extern "C" void kernel_launch(void* const* d_in, const int* in_sizes, int n_in,
                              void* d_out, int out_size) {
    const float* inputs   = (const float*)d_in[0];   // [512, 256] f32
    const float* features = (const float*)d_in[4];   // [65536, 256] f32
    float* out = (float*)d_out;

    cudaFuncSetAttribute(gemm_reduce_kernel,
                         cudaFuncAttributeMaxDynamicSharedMemorySize, SMEM_BYTES);

    prep_kernel<<<NROWS, DD>>>(inputs);
    gemm_reduce_kernel<<<NB, 256, SMEM_BYTES>>>(features);
    finalize_kernel<<<1, 256>>>(features, out);
}

// round 6
// speedup vs baseline: 2.2432x; 1.4340x over previous
#include <cuda_runtime.h>
#include <cuda_bf16.h>
#include <math_constants.h>
#include <cstdint>

// Problem constants (fixed by the dataset)
#define PP 16
#define CC 4
#define KK 8
#define NN 65536
#define DD 256
#define NROWS 64            // P*C
#define TILE_N 128
#define NB (NN / TILE_N)    // 512 blocks
#define INV_TEMP 20.0f
#define FSTR 264            // bf16 elements per smem tile row (pad 8 -> conflict-free)

// smem layout (bytes); tiles are [rows][FSTR] bf16, k-contiguous
#define SA 0                        // F:  128 x FSTR = 67584 B
#define SB (SA + 128 * FSTR * 2)    // Xh: 64 x FSTR  = 33792 B
#define SMEM_BYTES (SB + 64 * FSTR * 2)   // 101376 -> 2 CTAs/SM

// epilogue overlays (after mainloop __syncthreads)
#define SRED_STRIDE 66              // floats; sRed[n][pc] 128 x 66 (overlays SA)

// Scratch
__device__ float          g_xb[NROWS * DD];     // x-bar f32 (finalize)
__device__ __nv_bfloat16  g_xh[NROWS * DD];     // x-bar bf16
__device__ float g_pm[NROWS * NB];
__device__ float g_ps[NROWS * NB];
__device__ float g_pmin[NROWS * NB];

// ---------------------------------------------------------------------------
// helpers
// ---------------------------------------------------------------------------
__device__ __forceinline__ uint32_t smem_u32(const void* p) {
    uint32_t a;
    asm("{ .reg .u64 t; cvta.to.shared.u64 t, %1; cvt.u32.u64 %0, t; }"
        : "=r"(a) : "l"(p));
    return a;
}

__device__ __forceinline__ void ldsm4(uint32_t* d, uint32_t a) {
    asm volatile("ldmatrix.sync.aligned.m8n8.x4.shared.b16 {%0,%1,%2,%3}, [%4];"
                 : "=r"(d[0]), "=r"(d[1]), "=r"(d[2]), "=r"(d[3]) : "r"(a));
}

__device__ __forceinline__ void mma16816(float* c, const uint32_t* a,
                                         const uint32_t b0, const uint32_t b1) {
    asm volatile(
        "mma.sync.aligned.m16n8k16.row.col.f32.bf16.bf16.f32 "
        "{%0,%1,%2,%3}, {%4,%5,%6,%7}, {%8,%9}, {%0,%1,%2,%3};"
        : "+f"(c[0]), "+f"(c[1]), "+f"(c[2]), "+f"(c[3])
        : "r"(a[0]), "r"(a[1]), "r"(a[2]), "r"(a[3]), "r"(b0), "r"(b1));
}

__device__ __forceinline__ unsigned cvt2(float lo, float hi) {
    unsigned r;
    asm("cvt.rn.bf16x2.f32 %0, %1, %2;" : "=r"(r) : "f"(hi), "f"(lo));
    return r;
}

// ---------------------------------------------------------------------------
// Kernel A: normalize, K-average, emit f32 + bf16. grid=64, block=256.
// ---------------------------------------------------------------------------
__global__ void prep_kernel(const float* __restrict__ inputs) {
    const int pc = blockIdx.x;
    const int t  = threadIdx.x;
    __shared__ float wsum[8][8];

    float v[KK];
    #pragma unroll
    for (int k = 0; k < KK; k++)
        v[k] = inputs[(size_t)(pc * KK + k) * DD + t];

    float sq[KK];
    #pragma unroll
    for (int k = 0; k < KK; k++) sq[k] = v[k] * v[k];
    #pragma unroll
    for (int off = 16; off; off >>= 1)
        #pragma unroll
        for (int k = 0; k < KK; k++)
            sq[k] += __shfl_xor_sync(0xFFFFFFFFu, sq[k], off);
    if ((t & 31) == 0)
        #pragma unroll
        for (int k = 0; k < KK; k++) wsum[t >> 5][k] = sq[k];
    __syncthreads();

    float acc = 0.0f;
    #pragma unroll
    for (int k = 0; k < KK; k++) {
        float s2 = 0.0f;
        #pragma unroll
        for (int w = 0; w < 8; w++) s2 += wsum[w][k];
        acc += v[k] * rsqrtf(s2);
    }
    float xb = acc * (1.0f / (float)KK);
    g_xb[pc * DD + t] = xb;
    g_xh[pc * DD + t] = __float2bfloat16(xb);
}

// ---------------------------------------------------------------------------
// Kernel B: single-term bf16 warp-MMA GEMM + fused online-softmax/min partials.
// grid = NB (512), block = 256 (8 warps), 2 CTAs/SM.
// D[n=128][pc=64] = F[128,256] . Xbar^T.
// Warp tile 32(n) x 32(pc): warp w -> n in [(w&3)*32, +32), pc in [(w>>2)*32, +32)
// ---------------------------------------------------------------------------
__global__ void __launch_bounds__(256, 2)
gemm_reduce_kernel(const float* __restrict__ features) {
    extern __shared__ char smem[];
    const uint32_t sb = smem_u32(smem);
    const int t = threadIdx.x;
    const int b = blockIdx.x;
    const int n0 = b * TILE_N;

    // ---- load x-bar bf16 into smem tile ----
    {
        const uint2* xh4 = (const uint2*)g_xh;   // 4 bf16 per uint2
        #pragma unroll 4
        for (int i = t; i < NROWS * (DD / 4); i += 256) {
            int row  = i >> 6;          // 64 quads per row
            int colq = i & 63;
            *(uint2*)(smem + SB + (uint32_t)(row * FSTR + colq * 4) * 2) = xh4[i];
        }
    }
    // ---- load + convert features tile: f32 -> bf16 ----
    {
        const float4* f4 = (const float4*)(features + (size_t)n0 * DD);
        #pragma unroll 8
        for (int i = t; i < TILE_N * (DD / 4); i += 256) {
            float4 v = f4[i];
            int row  = i >> 6;
            int colq = i & 63;
            *(uint2*)(smem + SA + (uint32_t)(row * FSTR + colq * 4) * 2) =
                make_uint2(cvt2(v.x, v.y), cvt2(v.z, v.w));
        }
    }
    __syncthreads();

    const int lane  = t & 31;
    const int w     = t >> 5;
    const int nbase = (w & 3) * 32;      // feature-row base of warp tile
    const int pcbas = (w >> 2) * 32;     // pc-col base of warp tile

    // ldmatrix per-thread addresses
    const int aRow = nbase + (lane & 7) + ((lane >> 3) & 1) * 8;
    const int aCol = (lane >> 4) * 8;
    const int bRow = pcbas + (lane & 7) + (lane >> 4) * 8;
    const int bCol = ((lane >> 3) & 1) * 8;

    const uint32_t aB = sb + SA + (uint32_t)(aRow * FSTR + aCol) * 2;
    const uint32_t bB = sb + SB + (uint32_t)(bRow * FSTR + bCol) * 2;

    float acc[2][4][4];
    #pragma unroll
    for (int i = 0; i < 2; i++)
        #pragma unroll
        for (int j = 0; j < 4; j++)
            #pragma unroll
            for (int q = 0; q < 4; q++) acc[i][j][q] = 0.0f;

    #pragma unroll 4
    for (int k0 = 0; k0 < DD; k0 += 16) {
        uint32_t af[2][4], bf[2][4];
        ldsm4(af[0], aB + k0 * 2);
        ldsm4(af[1], aB + k0 * 2 + 16 * FSTR * 2);
        ldsm4(bf[0], bB + k0 * 2);
        ldsm4(bf[1], bB + k0 * 2 + 16 * FSTR * 2);
        #pragma unroll
        for (int mt = 0; mt < 2; mt++)
            #pragma unroll
            for (int ntp = 0; ntp < 2; ntp++) {
                mma16816(acc[mt][ntp * 2 + 0], af[mt], bf[ntp][0], bf[ntp][1]);
                mma16816(acc[mt][ntp * 2 + 1], af[mt], bf[ntp][2], bf[ntp][3]);
            }
    }
    __syncthreads();   // done reading tiles; safe to overlay epilogue buffers

    // ---- scatter accums to sRed[n][pc] (stride 66) ----
    float* sRed = (float*)smem;                      // 128*66 floats = 33792 B
    {
        const int r0 = lane >> 2;            // 0..7
        const int c0 = (lane & 3) * 2;       // 0,2,4,6
        #pragma unroll
        for (int mt = 0; mt < 2; mt++)
            #pragma unroll
            for (int nt = 0; nt < 4; nt++) {
                const int n  = nbase + mt * 16 + r0;
                const int pc = pcbas + nt * 8 + c0;
                *(float2*)(sRed + n * SRED_STRIDE + pc) =
                    make_float2(acc[mt][nt][0], acc[mt][nt][1]);
                *(float2*)(sRed + (n + 8) * SRED_STRIDE + pc) =
                    make_float2(acc[mt][nt][2], acc[mt][nt][3]);
            }
    }
    __syncthreads();

    // ---- fused reduction: per pc column over 128 n-rows ----
    float* cm = (float*)(smem + SB);
    float* cs = cm + 256;
    float* cn = cm + 512;
    {
        const int col = t & 63;              // pc
        const int seg = t >> 6;              // 32-row segment
        const float* src = sRed + (seg * 32) * SRED_STRIDE + col;
        float m = -CUDART_INF_F, s = 0.0f, mn = CUDART_INF_F;
        #pragma unroll 8
        for (int j = 0; j < 32; j++) {
            float v = src[j * SRED_STRIDE] * INV_TEMP;
            float nm = fmaxf(m, v);
            s = s * __expf(m - nm) + __expf(v - nm);
            m = nm;
            mn = fminf(mn, v);
        }
        cm[seg * 64 + col] = m;
        cs[seg * 64 + col] = s;
        cn[seg * 64 + col] = mn;
    }
    __syncthreads();

    if (t < 64) {
        float m = -CUDART_INF_F, s = 0.0f, mn = CUDART_INF_F;
        #pragma unroll
        for (int seg = 0; seg < 4; seg++) {
            float pm = cm[seg * 64 + t], ps = cs[seg * 64 + t], pn = cn[seg * 64 + t];
            float nm = fmaxf(m, pm);
            s = s * __expf(m - nm) + ps * __expf(pm - nm);
            m = nm;
            mn = fminf(mn, pn);
        }
        g_pm[t * NB + b]   = m;
        g_ps[t * NB + b]   = s;
        g_pmin[t * NB + b] = mn;
    }
}

// ---------------------------------------------------------------------------
// Kernel C: combine partials, compute own/pos, assemble the scalar loss.
// ---------------------------------------------------------------------------
__global__ void finalize_kernel(const float* __restrict__ features,
                                float* __restrict__ out) {
    __shared__ float rM[NROWS], rS[NROWS], rMin[NROWS], sOwn[NROWS];
    const int t = threadIdx.x;
    const int w = t >> 5, l = t & 31;

    for (int j = 0; j < 8; j++) {
        const int row = w * 8 + j;
        float m = -CUDART_INF_F, s = 0.0f, mn = CUDART_INF_F;
        for (int q = l; q < NB; q += 32) {
            float pm  = g_pm[row * NB + q];
            float ps  = g_ps[row * NB + q];
            float pmn = g_pmin[row * NB + q];
            float nm = fmaxf(m, pm);
            s = s * expf(m - nm) + ps * expf(pm - nm);
            m = nm;
            mn = fminf(mn, pmn);
        }
        #pragma unroll
        for (int off = 16; off; off >>= 1) {
            float mo  = __shfl_xor_sync(0xFFFFFFFFu, m,  off);
            float so  = __shfl_xor_sync(0xFFFFFFFFu, s,  off);
            float mno = __shfl_xor_sync(0xFFFFFFFFu, mn, off);
            float nm = fmaxf(m, mo);
            s = s * expf(m - nm) + so * expf(mo - nm);
            m = nm;
            mn = fminf(mn, mno);
        }
        if (l == 0) { rM[row] = m; rS[row] = s; rMin[row] = mn; }
    }
    __syncthreads();

    for (int j = 0; j < 8; j++) {
        const int pc = w * 8 + j;
        const int p  = pc >> 2;
        float d = 0.0f;
        for (int q = l; q < DD; q += 32)
            d = fmaf(g_xb[pc * DD + q], features[(size_t)p * DD + q], d);
        #pragma unroll
        for (int off = 16; off; off >>= 1)
            d += __shfl_xor_sync(0xFFFFFFFFu, d, off);
        if (l == 0) sOwn[pc] = d * INV_TEMP;
    }
    __syncthreads();

    float loss = 0.0f;
    if (t < PP) {
        const int p = t;
        float m = -CUDART_INF_F;
        #pragma unroll
        for (int c = 0; c < CC; c++) m = fmaxf(m, rM[p * CC + c]);
        float S = 0.0f;
        #pragma unroll
        for (int c = 0; c < CC; c++)
            S += rS[p * CC + c] * expf(rM[p * CC + c] - m);
        #pragma unroll
        for (int c = 0; c < CC; c++)
            S -= expf(rMin[p * CC + c] - m);
        float pos = CUDART_INF_F;
        #pragma unroll
        for (int c = 0; c < CC; c++) pos = fminf(pos, sOwn[p * CC + c]);
        S += expf(pos - m);
        loss = (m + logf(S)) - pos;
    }
    if (w == 0) {
        #pragma unroll
        for (int off = 16; off; off >>= 1)
            loss += __shfl_xor_sync(0xFFFFFFFFu, loss, off);
        if (l == 0) out[0] = loss * (1.0f / (float)PP);
    }
}

// ---------------------------------------------------------------------------
extern "C" void kernel_launch(void* const* d_in, const int* in_sizes, int n_in,
                              void* d_out, int out_size) {
    const float* inputs   = (const float*)d_in[0];   // [512, 256] f32
    const float* features = (const float*)d_in[4];   // [65536, 256] f32
    float* out = (float*)d_out;

    cudaFuncSetAttribute(gemm_reduce_kernel,
                         cudaFuncAttributeMaxDynamicSharedMemorySize, SMEM_BYTES);

    prep_kernel<<<NROWS, DD>>>(inputs);
    gemm_reduce_kernel<<<NB, 256, SMEM_BYTES>>>(features);
    finalize_kernel<<<1, 256>>>(features, out);
}

// round 7
// speedup vs baseline: 5.0244x; 2.2398x over previous
#include <cuda_runtime.h>
#include <cuda_bf16.h>
#include <math_constants.h>
#include <cstdint>

// Problem constants (fixed by the dataset)
#define PP 16
#define CC 4
#define KK 8
#define NN 65536
#define DD 256
#define NROWS 64            // P*C
#define TILE_N 128
#define NB (NN / TILE_N)    // 512 blocks
#define INV_TEMP 20.0f

#define KC 64               // k-chunk
#define FB_STR 72           // bf16 stride of F chunk rows (64 + 8 pad)
#define XSTR 264            // bf16 stride of X tile rows

// smem layout (bytes)
#define FB0 0                              // F chunk buf0: 128 x FB_STR x 2 = 18432
#define FB1 (FB0 + 128 * FB_STR * 2)       // buf1: 18432
#define SX  (FB1 + 128 * FB_STR * 2)       // X tile: 64 x XSTR x 2 = 33792
#define SMEM_BYTES (SX + 64 * XSTR * 2)    // 70656 -> 2 CTAs/SM easily

// epilogue overlays
#define SRED_STRIDE 66                     // sRed[n][pc]: 128 x 66 floats = 33792 (over FB0/FB1)

// Scratch
__device__ float          g_xb[NROWS * DD];
__device__ __nv_bfloat16  g_xh[NROWS * DD];
__device__ float g_pm[NROWS * NB];
__device__ float g_ps[NROWS * NB];
__device__ float g_pmin[NROWS * NB];
__device__ float g_rM[NROWS], g_rS[NROWS], g_rMin[NROWS], g_own[NROWS];

// ---------------------------------------------------------------------------
// helpers
// ---------------------------------------------------------------------------
__device__ __forceinline__ uint32_t smem_u32(const void* p) {
    uint32_t a;
    asm("{ .reg .u64 t; cvta.to.shared.u64 t, %1; cvt.u32.u64 %0, t; }"
        : "=r"(a) : "l"(p));
    return a;
}

__device__ __forceinline__ void ldsm4(uint32_t* d, uint32_t a) {
    asm volatile("ldmatrix.sync.aligned.m8n8.x4.shared.b16 {%0,%1,%2,%3}, [%4];"
                 : "=r"(d[0]), "=r"(d[1]), "=r"(d[2]), "=r"(d[3]) : "r"(a));
}

__device__ __forceinline__ void mma16816(float* c, const uint32_t* a,
                                         const uint32_t b0, const uint32_t b1) {
    asm volatile(
        "mma.sync.aligned.m16n8k16.row.col.f32.bf16.bf16.f32 "
        "{%0,%1,%2,%3}, {%4,%5,%6,%7}, {%8,%9}, {%0,%1,%2,%3};"
        : "+f"(c[0]), "+f"(c[1]), "+f"(c[2]), "+f"(c[3])
        : "r"(a[0]), "r"(a[1]), "r"(a[2]), "r"(a[3]), "r"(b0), "r"(b1));
}

__device__ __forceinline__ unsigned cvt2(float lo, float hi) {
    unsigned r;
    asm("cvt.rn.bf16x2.f32 %0, %1, %2;" : "=r"(r) : "f"(hi), "f"(lo));
    return r;
}

// ---------------------------------------------------------------------------
// Kernel A: normalize, K-average, emit f32 + bf16. grid=64, block=256.
// ---------------------------------------------------------------------------
__global__ void prep_kernel(const float* __restrict__ inputs) {
    const int pc = blockIdx.x;
    const int t  = threadIdx.x;
    __shared__ float wsum[8][8];

    float v[KK];
    #pragma unroll
    for (int k = 0; k < KK; k++)
        v[k] = inputs[(size_t)(pc * KK + k) * DD + t];

    float sq[KK];
    #pragma unroll
    for (int k = 0; k < KK; k++) sq[k] = v[k] * v[k];
    #pragma unroll
    for (int off = 16; off; off >>= 1)
        #pragma unroll
        for (int k = 0; k < KK; k++)
            sq[k] += __shfl_xor_sync(0xFFFFFFFFu, sq[k], off);
    if ((t & 31) == 0)
        #pragma unroll
        for (int k = 0; k < KK; k++) wsum[t >> 5][k] = sq[k];
    __syncthreads();

    float acc = 0.0f;
    #pragma unroll
    for (int k = 0; k < KK; k++) {
        float s2 = 0.0f;
        #pragma unroll
        for (int w = 0; w < 8; w++) s2 += wsum[w][k];
        acc += v[k] * rsqrtf(s2);
    }
    float xb = acc * (1.0f / (float)KK);
    g_xb[pc * DD + t] = xb;
    g_xh[pc * DD + t] = __float2bfloat16(xb);
}

// ---------------------------------------------------------------------------
// Kernel B: pipelined bf16 warp-MMA GEMM + fused online-softmax/min partials.
// grid = NB (512), block = 256 (8 warps), 2 CTAs/SM.
// K pipelined in 4 chunks of 64 with double-buffered F tiles.
// ---------------------------------------------------------------------------
__global__ void __launch_bounds__(256, 2)
gemm_reduce_kernel(const float* __restrict__ features) {
    extern __shared__ char smem[];
    const uint32_t sb = smem_u32(smem);
    const int t = threadIdx.x;
    const int b = blockIdx.x;
    const int n0 = b * TILE_N;

    // ---- load x-bar bf16 tile (full K) ----
    {
        const uint2* xh4 = (const uint2*)g_xh;
        #pragma unroll 4
        for (int i = t; i < NROWS * (DD / 4); i += 256) {
            int row  = i >> 6;
            int colq = i & 63;
            *(uint2*)(smem + SX + (uint32_t)(row * XSTR + colq * 4) * 2) = xh4[i];
        }
    }

    const float4* f4 = (const float4*)(features + (size_t)n0 * DD);
    float4 R[8];

    // ---- prologue: chunk 0 load + store ----
    #pragma unroll
    for (int j = 0; j < 8; j++) {
        int idx = t + 256 * j;
        R[j] = f4[(idx >> 4) * 64 + (idx & 15)];
    }
    #pragma unroll
    for (int j = 0; j < 8; j++) {
        int idx = t + 256 * j;
        int row = idx >> 4, q = idx & 15;
        *(uint2*)(smem + FB0 + (uint32_t)(row * FB_STR + q * 4) * 2) =
            make_uint2(cvt2(R[j].x, R[j].y), cvt2(R[j].z, R[j].w));
    }
    __syncthreads();

    const int lane  = t & 31;
    const int w     = t >> 5;
    const int nbase = (w & 3) * 32;
    const int pcbas = (w >> 2) * 32;

    const int aRow = nbase + (lane & 7) + ((lane >> 3) & 1) * 8;
    const int aCol = (lane >> 4) * 8;
    const int bRow = pcbas + (lane & 7) + (lane >> 4) * 8;
    const int bCol = ((lane >> 3) & 1) * 8;

    const uint32_t aOffL = (uint32_t)(aRow * FB_STR + aCol) * 2;
    const uint32_t bB = sb + SX + (uint32_t)(bRow * XSTR + bCol) * 2;

    float acc[2][4][4];
    #pragma unroll
    for (int i = 0; i < 2; i++)
        #pragma unroll
        for (int j = 0; j < 4; j++)
            #pragma unroll
            for (int q = 0; q < 4; q++) acc[i][j][q] = 0.0f;

    #pragma unroll
    for (int c = 0; c < 4; c++) {
        // issue next chunk's global loads early (hide latency under MMAs)
        if (c < 3) {
            #pragma unroll
            for (int j = 0; j < 8; j++) {
                int idx = t + 256 * j;
                R[j] = f4[(idx >> 4) * 64 + (c + 1) * 16 + (idx & 15)];
            }
        }
        const uint32_t aBuf = sb + ((c & 1) ? FB1 : FB0) + aOffL;
        #pragma unroll
        for (int kst = 0; kst < 4; kst++) {
            uint32_t af[2][4], bfr[2][4];
            ldsm4(af[0], aBuf + kst * 32);
            ldsm4(af[1], aBuf + kst * 32 + 16 * FB_STR * 2);
            ldsm4(bfr[0], bB + (c * KC + kst * 16) * 2);
            ldsm4(bfr[1], bB + (c * KC + kst * 16) * 2 + 16 * XSTR * 2);
            #pragma unroll
            for (int mt = 0; mt < 2; mt++)
                #pragma unroll
                for (int ntp = 0; ntp < 2; ntp++) {
                    mma16816(acc[mt][ntp * 2 + 0], af[mt], bfr[ntp][0], bfr[ntp][1]);
                    mma16816(acc[mt][ntp * 2 + 1], af[mt], bfr[ntp][2], bfr[ntp][3]);
                }
        }
        if (c < 3) {
            __syncthreads();   // all warps done reading target buffer (chunk c-1)
            const int dst = (c & 1) ? FB0 : FB1;
            #pragma unroll
            for (int j = 0; j < 8; j++) {
                int idx = t + 256 * j;
                int row = idx >> 4, q = idx & 15;
                *(uint2*)(smem + dst + (uint32_t)(row * FB_STR + q * 4) * 2) =
                    make_uint2(cvt2(R[j].x, R[j].y), cvt2(R[j].z, R[j].w));
            }
            __syncthreads();
        }
    }
    __syncthreads();   // safe to overlay epilogue buffers

    // ---- scatter accums to sRed[n][pc] (stride 66), overlays F buffers ----
    float* sRed = (float*)smem;
    {
        const int r0 = lane >> 2;
        const int c0 = (lane & 3) * 2;
        #pragma unroll
        for (int mt = 0; mt < 2; mt++)
            #pragma unroll
            for (int nt = 0; nt < 4; nt++) {
                const int n  = nbase + mt * 16 + r0;
                const int pc = pcbas + nt * 8 + c0;
                *(float2*)(sRed + n * SRED_STRIDE + pc) =
                    make_float2(acc[mt][nt][0], acc[mt][nt][1]);
                *(float2*)(sRed + (n + 8) * SRED_STRIDE + pc) =
                    make_float2(acc[mt][nt][2], acc[mt][nt][3]);
            }
    }
    __syncthreads();

    // ---- fused reduction: per pc column over 128 n-rows ----
    float* cm = (float*)(smem + SX);
    float* cs = cm + 256;
    float* cn = cm + 512;
    {
        const int col = t & 63;
        const int seg = t >> 6;
        const float* src = sRed + (seg * 32) * SRED_STRIDE + col;
        float m = -CUDART_INF_F, s = 0.0f, mn = CUDART_INF_F;
        #pragma unroll 8
        for (int j = 0; j < 32; j++) {
            float v = src[j * SRED_STRIDE] * INV_TEMP;
            float nm = fmaxf(m, v);
            s = s * __expf(m - nm) + __expf(v - nm);
            m = nm;
            mn = fminf(mn, v);
        }
        cm[seg * 64 + col] = m;
        cs[seg * 64 + col] = s;
        cn[seg * 64 + col] = mn;
    }
    __syncthreads();

    if (t < 64) {
        float m = -CUDART_INF_F, s = 0.0f, mn = CUDART_INF_F;
        #pragma unroll
        for (int seg = 0; seg < 4; seg++) {
            float pm = cm[seg * 64 + t], ps = cs[seg * 64 + t], pn = cn[seg * 64 + t];
            float nm = fmaxf(m, pm);
            s = s * __expf(m - nm) + ps * __expf(pm - nm);
            m = nm;
            mn = fminf(mn, pn);
        }
        g_pm[t * NB + b]   = m;
        g_ps[t * NB + b]   = s;
        g_pmin[t * NB + b] = mn;
    }
}

// ---------------------------------------------------------------------------
// Kernel C1: per-row combine of the 512 partials + own-dot. grid=64, block=128.
// ---------------------------------------------------------------------------
__global__ void combine_kernel(const float* __restrict__ features) {
    const int row = blockIdx.x;
    const int t = threadIdx.x;       // 128
    const int w = t >> 5, l = t & 31;
    __shared__ float pm[4], ps[4], pn[4], pd[4];

    float m = -CUDART_INF_F, s = 0.0f, mn = CUDART_INF_F;
    #pragma unroll
    for (int j = 0; j < 4; j++) {
        const int q = t + 128 * j;
        float am = g_pm[row * NB + q];
        float as = g_ps[row * NB + q];
        float an = g_pmin[row * NB + q];
        float nm = fmaxf(m, am);
        s = s * __expf(m - nm) + as * __expf(am - nm);
        m = nm;
        mn = fminf(mn, an);
    }
    #pragma unroll
    for (int off = 16; off; off >>= 1) {
        float mo  = __shfl_xor_sync(0xFFFFFFFFu, m,  off);
        float so  = __shfl_xor_sync(0xFFFFFFFFu, s,  off);
        float mno = __shfl_xor_sync(0xFFFFFFFFu, mn, off);
        float nm = fmaxf(m, mo);
        s = s * __expf(m - nm) + so * __expf(mo - nm);
        m = nm;
        mn = fminf(mn, mno);
    }
    // own-dot partial
    const int p = row >> 2;
    float d = g_xb[row * DD + t] * features[(size_t)p * DD + t]
            + g_xb[row * DD + t + 128] * features[(size_t)p * DD + t + 128];
    #pragma unroll
    for (int off = 16; off; off >>= 1)
        d += __shfl_xor_sync(0xFFFFFFFFu, d, off);

    if (l == 0) { pm[w] = m; ps[w] = s; pn[w] = mn; pd[w] = d; }
    __syncthreads();

    if (t == 0) {
        float M = pm[0], S = ps[0], MN = pn[0], D = pd[0];
        #pragma unroll
        for (int i = 1; i < 4; i++) {
            float nm = fmaxf(M, pm[i]);
            S = S * expf(M - nm) + ps[i] * expf(pm[i] - nm);
            M = nm;
            MN = fminf(MN, pn[i]);
            D += pd[i];
        }
        g_rM[row] = M; g_rS[row] = S; g_rMin[row] = MN;
        g_own[row] = D * INV_TEMP;
    }
}

// ---------------------------------------------------------------------------
// Kernel C2: assemble scalar loss. 1 block, 32 threads.
// ---------------------------------------------------------------------------
__global__ void final_kernel(float* __restrict__ out) {
    const int t = threadIdx.x;
    float loss = 0.0f;
    if (t < PP) {
        const int p = t;
        float m = -CUDART_INF_F;
        #pragma unroll
        for (int c = 0; c < CC; c++) m = fmaxf(m, g_rM[p * CC + c]);
        float S = 0.0f;
        #pragma unroll
        for (int c = 0; c < CC; c++)
            S += g_rS[p * CC + c] * expf(g_rM[p * CC + c] - m);
        #pragma unroll
        for (int c = 0; c < CC; c++)
            S -= expf(g_rMin[p * CC + c] - m);
        float pos = CUDART_INF_F;
        #pragma unroll
        for (int c = 0; c < CC; c++) pos = fminf(pos, g_own[p * CC + c]);
        S += expf(pos - m);
        loss = (m + logf(S)) - pos;
    }
    #pragma unroll
    for (int off = 16; off; off >>= 1)
        loss += __shfl_xor_sync(0xFFFFFFFFu, loss, off);
    if (t == 0) out[0] = loss * (1.0f / (float)PP);
}

// ---------------------------------------------------------------------------
extern "C" void kernel_launch(void* const* d_in, const int* in_sizes, int n_in,
                              void* d_out, int out_size) {
    const float* inputs   = (const float*)d_in[0];   // [512, 256] f32
    const float* features = (const float*)d_in[4];   // [65536, 256] f32
    float* out = (float*)d_out;

    cudaFuncSetAttribute(gemm_reduce_kernel,
                         cudaFuncAttributeMaxDynamicSharedMemorySize, SMEM_BYTES);

    prep_kernel<<<NROWS, DD>>>(inputs);
    gemm_reduce_kernel<<<NB, 256, SMEM_BYTES>>>(features);
    combine_kernel<<<NROWS, 128>>>(features);
    final_kernel<<<1, 32>>>(out);
}